// round 1
// baseline (speedup 1.0000x reference)
#include <cuda_runtime.h>
#include <math.h>

#define BB 2
#define CC 128
#define LL 56
#define PL 3136      // 56*56
#define SP 175616    // 56^3
#define SLEN 512     // 8*8*8 pooled spatial

// Scratch (static device globals; no allocation)
__device__ float g_sax[3][BB][CC][LL];   // axis means: 0=d,1=h,2=w
__device__ float g_gate[3][BB][CC][LL];  // sigmoid gates
__device__ float g_y[BB][CC][SLEN];      // pooled tensor
__device__ float g_stat[4];              // mu0,rstd0,mu1,rstd1
__device__ float g_ca[BB][CC];           // channel attention scalars

// ---------------------------------------------------------------------------
// K1: axis means. One block per (b,c). blockDim (64,8)=512.
// thread: w = tx (<56), rows h = ty + 8*r, r in [0,7)
// ---------------------------------------------------------------------------
__global__ void k1_axis_means(const float* __restrict__ x) {
    int bc = blockIdx.x;                  // b*128 + c
    const float* xp = x + (size_t)bc * SP;
    __shared__ float sd[LL], sh_[LL], sw_[LL];
    int tx = threadIdx.x, ty = threadIdx.y;
    int tid = ty * 64 + tx;
    if (tid < LL) { sd[tid] = 0.f; sh_[tid] = 0.f; sw_[tid] = 0.f; }
    __syncthreads();
    bool act = tx < LL;
    int lane = tid & 31;

    float acc_w = 0.f;
    float acc_h[7];
#pragma unroll
    for (int r = 0; r < 7; ++r) acc_h[r] = 0.f;

    for (int d = 0; d < LL; ++d) {
        float v[7];
#pragma unroll
        for (int r = 0; r < 7; ++r) {
            int h = ty + 8 * r;
            v[r] = act ? xp[(size_t)d * PL + h * LL + tx] : 0.f;
        }
        float plane = 0.f;
#pragma unroll
        for (int r = 0; r < 7; ++r) {
            plane += v[r];
            acc_h[r] += v[r];
        }
        acc_w += plane;
        // one warp reduce per d (warps have uniform ty)
        float s = plane;
#pragma unroll
        for (int o = 16; o; o >>= 1) s += __shfl_down_sync(0xffffffffu, s, o);
        if (lane == 0) atomicAdd(&sd[d], s);
    }
    // per-h reductions (7 per warp total)
#pragma unroll
    for (int r = 0; r < 7; ++r) {
        float s = acc_h[r];
#pragma unroll
        for (int o = 16; o; o >>= 1) s += __shfl_down_sync(0xffffffffu, s, o);
        if (lane == 0) atomicAdd(&sh_[ty + 8 * r], s);
    }
    if (act) atomicAdd(&sw_[tx], acc_w);
    __syncthreads();
    if (tid < LL) {
        int b = bc >> 7, c = bc & 127;
        const float inv = 1.0f / (float)PL;
        g_sax[0][b][c][tid] = sd[tid] * inv;
        g_sax[1][b][c][tid] = sh_[tid] * inv;
        g_sax[2][b][c][tid] = sw_[tid] * inv;
    }
}

// ---------------------------------------------------------------------------
// K2: depthwise conv branches + GroupNorm(4) + sigmoid.
// grid = 3 axes * 2 batch * 4 groups = 24 blocks, 256 threads.
// ---------------------------------------------------------------------------
__global__ void k2_gates(const float* __restrict__ wl, const float* __restrict__ bl,
                         const float* __restrict__ ws, const float* __restrict__ bs,
                         const float* __restrict__ wm, const float* __restrict__ bm,
                         const float* __restrict__ wg, const float* __restrict__ bg,
                         const float* __restrict__ gd, const float* __restrict__ btd,
                         const float* __restrict__ gh, const float* __restrict__ bth,
                         const float* __restrict__ gw, const float* __restrict__ btw) {
    int idx = blockIdx.x;
    int axis = idx >> 3;
    int b = (idx >> 2) & 1;
    int g = idx & 3;
    const int ksz[4] = {3, 5, 7, 9};
    const float* wptr[4] = {wl, ws, wm, wg};
    const float* bptr[4] = {bl, bs, bm, bg};
    const float* gam[3] = {gd, gh, gw};
    const float* bet[3] = {btd, bth, btw};
    int k = ksz[g], half = k >> 1;

    __shared__ float s_in[32][LL];
    __shared__ float s_out[32][LL];
    __shared__ float s_w[32 * 9];
    __shared__ float s_b[32];
    __shared__ float red[2];
    __shared__ float rs[8], rq[8];

    int tid = threadIdx.x;
    for (int i = tid; i < 32 * LL; i += 256) {
        int cc = i / LL, l = i % LL;
        s_in[cc][l] = g_sax[axis][b][g * 32 + cc][l];
    }
    for (int i = tid; i < 32 * k; i += 256) s_w[i] = wptr[g][i];
    if (tid < 32) s_b[tid] = bptr[g][tid];
    __syncthreads();

    float lsum = 0.f, lsq = 0.f;
    for (int i = tid; i < 32 * LL; i += 256) {
        int cc = i / LL, l = i % LL;
        float acc = s_b[cc];
        for (int j = 0; j < k; ++j) {
            int p = l + j - half;
            if (p >= 0 && p < LL) acc += s_w[cc * k + j] * s_in[cc][p];
        }
        s_out[cc][l] = acc;
        lsum += acc;
        lsq += acc * acc;
    }
#pragma unroll
    for (int o = 16; o; o >>= 1) {
        lsum += __shfl_down_sync(0xffffffffu, lsum, o);
        lsq  += __shfl_down_sync(0xffffffffu, lsq, o);
    }
    if ((tid & 31) == 0) { rs[tid >> 5] = lsum; rq[tid >> 5] = lsq; }
    __syncthreads();
    if (tid == 0) {
        float S = 0.f, Q = 0.f;
        for (int i = 0; i < 8; ++i) { S += rs[i]; Q += rq[i]; }
        float n = 32.f * LL;
        float mu = S / n;
        float var = Q / n - mu * mu;
        red[0] = mu;
        red[1] = rsqrtf(var + 1e-5f);
    }
    __syncthreads();
    float mu = red[0], rstd = red[1];
    for (int i = tid; i < 32 * LL; i += 256) {
        int cc = i / LL, l = i % LL;
        int c = g * 32 + cc;
        float v = (s_out[cc][l] - mu) * rstd * gam[axis][c] + bet[axis][c];
        g_gate[axis][b][c][l] = 1.f / (1.f + expf(-v));
    }
}

// ---------------------------------------------------------------------------
// K3: xg = x * gd*gh*gw -> out, plus 7^3 avg-pool into g_y.
// grid = (b*C+c)*8 + dd = 2048 blocks; blockDim (64,8)=512.
// thread: w = tx (<56), hh = ty, rows h = ty*7 + rr.
// ---------------------------------------------------------------------------
__global__ void k3_gate_pool(const float* __restrict__ x, float* __restrict__ out) {
    int id = blockIdx.x;
    int dd = id & 7;
    int bc = id >> 3;
    int b = bc >> 7, c = bc & 127;
    const float* xp = x + (size_t)bc * SP;
    float* op = out + (size_t)bc * SP;

    __shared__ float sgh[LL];
    __shared__ float buf[8 * 64];
    int tx = threadIdx.x, ty = threadIdx.y;
    int tid = ty * 64 + tx;
    if (tid < LL) sgh[tid] = g_gate[1][b][c][tid];
    __syncthreads();

    bool act = tx < LL;
    float gww = act ? g_gate[2][b][c][tx] : 0.f;
    float acc = 0.f;
    for (int i = 0; i < 7; ++i) {
        int d = dd * 7 + i;
        float gdd = g_gate[0][b][c][d];
#pragma unroll
        for (int rr = 0; rr < 7; ++rr) {
            int h = ty * 7 + rr;
            size_t off = (size_t)d * PL + h * LL + tx;
            if (act) {
                float v = xp[off] * gdd * sgh[h] * gww;
                op[off] = v;
                acc += v;
            }
        }
    }
    buf[tid] = acc;
    __syncthreads();
    if (tid < 64) {
        int hh = tid >> 3, ww = tid & 7;
        float s = 0.f;
#pragma unroll
        for (int j = 0; j < 7; ++j) s += buf[hh * 64 + ww * 7 + j];
        g_y[b][c][dd * 64 + hh * 8 + ww] = s * (1.0f / 343.0f);
    }
}

// ---------------------------------------------------------------------------
// K4a: GroupNorm(1) stats of y per batch (65536 elems). grid=2, 512 threads.
// ---------------------------------------------------------------------------
__global__ void k4a_ystats() {
    int b = blockIdx.x;
    int tid = threadIdx.x;
    const float* yp = &g_y[b][0][0];
    double s = 0.0, q = 0.0;
    for (int i = tid; i < CC * SLEN; i += 512) {
        float v = yp[i];
        s += v;
        q += (double)v * v;
    }
    __shared__ double rs[16], rq[16];
#pragma unroll
    for (int o = 16; o; o >>= 1) {
        s += __shfl_down_sync(0xffffffffu, s, o);
        q += __shfl_down_sync(0xffffffffu, q, o);
    }
    if ((tid & 31) == 0) { rs[tid >> 5] = s; rq[tid >> 5] = q; }
    __syncthreads();
    if (tid == 0) {
        double S = 0.0, Q = 0.0;
        for (int i = 0; i < 16; ++i) { S += rs[i]; Q += rq[i]; }
        double n = (double)(CC * SLEN);
        double mu = S / n;
        double var = Q / n - mu * mu;
        g_stat[b * 2] = (float)mu;
        g_stat[b * 2 + 1] = (float)(1.0 / sqrt(var + 1e-5));
    }
}

// ---------------------------------------------------------------------------
// K4b: channel attention per (b, head). grid=16, 256 threads.
// o.mean(s) = attn @ v.mean(s), so only Gram matrix + v row-means needed.
// ---------------------------------------------------------------------------
__global__ void k4b_attn(const float* __restrict__ gn, const float* __restrict__ btn,
                         const float* __restrict__ wq, const float* __restrict__ wk,
                         const float* __restrict__ wv) {
    int b = blockIdx.x >> 3;
    int head = blockIdx.x & 7;
    int c0 = head * 16;
    __shared__ float yn[16][513];
    __shared__ float ps[16][16];
    __shared__ float G[16][16];
    __shared__ float vmean[16];
    int tid = threadIdx.x;
    float mu = g_stat[b * 2], rstd = g_stat[b * 2 + 1];

    for (int i = tid; i < 16 * SLEN; i += 256) {
        int j = i >> 9, s = i & 511;
        int c = c0 + j;
        yn[j][s] = (g_y[b][c][s] - mu) * rstd * gn[c] + btn[c];
    }
    __syncthreads();
    // row partial sums for v_mean
    {
        int j = tid >> 4, seg = tid & 15;
        float s = 0.f;
        for (int t = 0; t < 32; ++t) s += yn[j][seg * 32 + t];
        ps[j][seg] = s;
    }
    __syncthreads();
    if (tid < 16) {
        float t = 0.f;
        for (int i = 0; i < 16; ++i) t += ps[tid][i];
        vmean[tid] = wv[c0 + tid] * t * (1.0f / 512.0f);
    }
    // Gram matrix
    {
        int i = tid >> 4, j = tid & 15;
        float acc = 0.f;
        for (int s = 0; s < SLEN; ++s) acc += yn[i][s] * yn[j][s];
        G[i][j] = acc;
    }
    __syncthreads();
    if (tid < 16) {
        int i = tid;
        float qi = wq[c0 + i] * 0.25f;  // includes HD^-0.5
        float sc[16];
        float m = -1e30f;
#pragma unroll
        for (int j = 0; j < 16; ++j) {
            sc[j] = qi * wk[c0 + j] * G[i][j];
            m = fmaxf(m, sc[j]);
        }
        float sum = 0.f;
#pragma unroll
        for (int j = 0; j < 16; ++j) {
            sc[j] = expf(sc[j] - m);
            sum += sc[j];
        }
        float o = 0.f;
#pragma unroll
        for (int j = 0; j < 16; ++j) o += sc[j] * vmean[j];
        o /= sum;
        g_ca[b][c0 + i] = 1.f / (1.f + expf(-o));
    }
}

// ---------------------------------------------------------------------------
// K5: out *= ca[b][c] in place. grid = 2048, 256 threads, float4.
// ---------------------------------------------------------------------------
__global__ void k5_scale(float* __restrict__ out) {
    int id = blockIdx.x;
    int bc = id >> 3;
    int ch = id & 7;
    float s = g_ca[bc >> 7][bc & 127];
    float4* p = reinterpret_cast<float4*>(out + (size_t)bc * SP) + ch * 5488;
    int tid = threadIdx.x;
    for (int i = tid; i < 5488; i += 256) {
        float4 v = p[i];
        v.x *= s; v.y *= s; v.z *= s; v.w *= s;
        p[i] = v;
    }
}

// ---------------------------------------------------------------------------
extern "C" void kernel_launch(void* const* d_in, const int* in_sizes, int n_in,
                              void* d_out, int out_size) {
    const float* x = (const float*)d_in[0];
    float* out = (float*)d_out;

    k1_axis_means<<<BB * CC, dim3(64, 8)>>>(x);
    k2_gates<<<24, 256>>>(
        (const float*)d_in[1], (const float*)d_in[2],
        (const float*)d_in[3], (const float*)d_in[4],
        (const float*)d_in[5], (const float*)d_in[6],
        (const float*)d_in[7], (const float*)d_in[8],
        (const float*)d_in[9], (const float*)d_in[10],
        (const float*)d_in[11], (const float*)d_in[12],
        (const float*)d_in[13], (const float*)d_in[14]);
    k3_gate_pool<<<BB * CC * 8, dim3(64, 8)>>>(x, out);
    k4a_ystats<<<BB, 512>>>();
    k4b_attn<<<BB * 8, 256>>>(
        (const float*)d_in[15], (const float*)d_in[16],
        (const float*)d_in[17], (const float*)d_in[18],
        (const float*)d_in[19]);
    k5_scale<<<BB * CC * 8, 256>>>(out);
}

// round 2
// speedup vs baseline: 1.7538x; 1.7538x over previous
#include <cuda_runtime.h>
#include <math.h>

#define BB 2
#define CC 128
#define LL 56
#define PL 3136      // 56*56
#define SP 175616    // 56^3
#define SLEN 512     // 8*8*8 pooled spatial

// Scratch (static device globals; no allocation)
__device__ float g_sax[3][BB][CC][LL];    // axis means: 0=d,1=h,2=w
__device__ float g_gate[3][BB][CC][LL];   // sigmoid gates
__device__ float g_y[BB][CC][SLEN];       // pooled tensor
__device__ double g_part[BB * CC * 8][2]; // per-K3-block (sum, sumsq) of y
__device__ float g_ca[BB][CC];            // channel attention scalars

// ---------------------------------------------------------------------------
// K1: axis means. One block per (b,c). blockDim (64,8)=512.
// ---------------------------------------------------------------------------
__global__ void k1_axis_means(const float* __restrict__ x) {
    int bc = blockIdx.x;                  // b*128 + c
    const float* xp = x + (size_t)bc * SP;
    __shared__ float sd[LL], sh_[LL], sw_[LL];
    int tx = threadIdx.x, ty = threadIdx.y;
    int tid = ty * 64 + tx;
    if (tid < LL) { sd[tid] = 0.f; sh_[tid] = 0.f; sw_[tid] = 0.f; }
    __syncthreads();
    bool act = tx < LL;
    int lane = tid & 31;

    float acc_w = 0.f;
    float acc_h[7];
#pragma unroll
    for (int r = 0; r < 7; ++r) acc_h[r] = 0.f;

    for (int d = 0; d < LL; ++d) {
        float v[7];
#pragma unroll
        for (int r = 0; r < 7; ++r) {
            int h = ty + 8 * r;
            v[r] = act ? xp[(size_t)d * PL + h * LL + tx] : 0.f;
        }
        float plane = 0.f;
#pragma unroll
        for (int r = 0; r < 7; ++r) {
            plane += v[r];
            acc_h[r] += v[r];
        }
        acc_w += plane;
        float s = plane;
#pragma unroll
        for (int o = 16; o; o >>= 1) s += __shfl_down_sync(0xffffffffu, s, o);
        if (lane == 0) atomicAdd(&sd[d], s);
    }
#pragma unroll
    for (int r = 0; r < 7; ++r) {
        float s = acc_h[r];
#pragma unroll
        for (int o = 16; o; o >>= 1) s += __shfl_down_sync(0xffffffffu, s, o);
        if (lane == 0) atomicAdd(&sh_[ty + 8 * r], s);
    }
    if (act) atomicAdd(&sw_[tx], acc_w);
    __syncthreads();
    if (tid < LL) {
        int b = bc >> 7, c = bc & 127;
        const float inv = 1.0f / (float)PL;
        g_sax[0][b][c][tid] = sd[tid] * inv;
        g_sax[1][b][c][tid] = sh_[tid] * inv;
        g_sax[2][b][c][tid] = sw_[tid] * inv;
    }
}

// ---------------------------------------------------------------------------
// K2: depthwise conv branches + GroupNorm(4) + sigmoid. grid=24, 256 threads.
// ---------------------------------------------------------------------------
__global__ void k2_gates(const float* __restrict__ wl, const float* __restrict__ bl,
                         const float* __restrict__ ws, const float* __restrict__ bs,
                         const float* __restrict__ wm, const float* __restrict__ bm,
                         const float* __restrict__ wg, const float* __restrict__ bg,
                         const float* __restrict__ gd, const float* __restrict__ btd,
                         const float* __restrict__ gh, const float* __restrict__ bth,
                         const float* __restrict__ gw, const float* __restrict__ btw) {
    int idx = blockIdx.x;
    int axis = idx >> 3;
    int b = (idx >> 2) & 1;
    int g = idx & 3;
    const int ksz[4] = {3, 5, 7, 9};
    const float* wptr[4] = {wl, ws, wm, wg};
    const float* bptr[4] = {bl, bs, bm, bg};
    const float* gam[3] = {gd, gh, gw};
    const float* bet[3] = {btd, bth, btw};
    int k = ksz[g], half = k >> 1;

    __shared__ float s_in[32][LL];
    __shared__ float s_out[32][LL];
    __shared__ float s_w[32 * 9];
    __shared__ float s_b[32];
    __shared__ float red[2];
    __shared__ float rs[8], rq[8];

    int tid = threadIdx.x;
    for (int i = tid; i < 32 * LL; i += 256) {
        int cc = i / LL, l = i % LL;
        s_in[cc][l] = g_sax[axis][b][g * 32 + cc][l];
    }
    for (int i = tid; i < 32 * k; i += 256) s_w[i] = wptr[g][i];
    if (tid < 32) s_b[tid] = bptr[g][tid];
    __syncthreads();

    float lsum = 0.f, lsq = 0.f;
    for (int i = tid; i < 32 * LL; i += 256) {
        int cc = i / LL, l = i % LL;
        float acc = s_b[cc];
        for (int j = 0; j < k; ++j) {
            int p = l + j - half;
            if (p >= 0 && p < LL) acc += s_w[cc * k + j] * s_in[cc][p];
        }
        s_out[cc][l] = acc;
        lsum += acc;
        lsq += acc * acc;
    }
#pragma unroll
    for (int o = 16; o; o >>= 1) {
        lsum += __shfl_down_sync(0xffffffffu, lsum, o);
        lsq  += __shfl_down_sync(0xffffffffu, lsq, o);
    }
    if ((tid & 31) == 0) { rs[tid >> 5] = lsum; rq[tid >> 5] = lsq; }
    __syncthreads();
    if (tid == 0) {
        float S = 0.f, Q = 0.f;
        for (int i = 0; i < 8; ++i) { S += rs[i]; Q += rq[i]; }
        float n = 32.f * LL;
        float mu = S / n;
        float var = Q / n - mu * mu;
        red[0] = mu;
        red[1] = rsqrtf(var + 1e-5f);
    }
    __syncthreads();
    float mu = red[0], rstd = red[1];
    for (int i = tid; i < 32 * LL; i += 256) {
        int cc = i / LL, l = i % LL;
        int c = g * 32 + cc;
        float v = (s_out[cc][l] - mu) * rstd * gam[axis][c] + bet[axis][c];
        g_gate[axis][b][c][l] = 1.f / (1.f + expf(-v));
    }
}

// ---------------------------------------------------------------------------
// K3: pool gated x into y (NO xg store), emit deterministic (sum,sumsq) partial.
// grid = (b*C+c)*8 + dd = 2048 blocks; blockDim (64,8)=512.
// ---------------------------------------------------------------------------
__global__ void k3_pool(const float* __restrict__ x) {
    int id = blockIdx.x;
    int dd = id & 7;
    int bc = id >> 3;
    int b = bc >> 7, c = bc & 127;
    const float* xp = x + (size_t)bc * SP;

    __shared__ float sgh[LL];
    __shared__ float buf[8 * 64];
    __shared__ double pr[2][2];
    int tx = threadIdx.x, ty = threadIdx.y;
    int tid = ty * 64 + tx;
    if (tid < LL) sgh[tid] = g_gate[1][b][c][tid];
    __syncthreads();

    bool act = tx < LL;
    float gww = act ? g_gate[2][b][c][tx] : 0.f;
    float acc = 0.f;
    for (int i = 0; i < 7; ++i) {
        int d = dd * 7 + i;
        float gdd = g_gate[0][b][c][d];
#pragma unroll
        for (int rr = 0; rr < 7; ++rr) {
            int h = ty * 7 + rr;
            if (act) {
                float v = xp[(size_t)d * PL + h * LL + tx] * gdd * sgh[h] * gww;
                acc += v;
            }
        }
    }
    buf[tid] = acc;
    __syncthreads();
    if (tid < 64) {
        int hh = tid >> 3, ww = tid & 7;
        float s = 0.f;
#pragma unroll
        for (int j = 0; j < 7; ++j) s += buf[hh * 64 + ww * 7 + j];
        float yv = s * (1.0f / 343.0f);
        g_y[b][c][dd * 64 + hh * 8 + ww] = yv;
        // deterministic partial stats over this block's 64 y values
        double sv = yv, sq = (double)yv * yv;
#pragma unroll
        for (int o = 16; o; o >>= 1) {
            sv += __shfl_down_sync(0xffffffffu, sv, o);
            sq += __shfl_down_sync(0xffffffffu, sq, o);
        }
        if ((tid & 31) == 0) { pr[tid >> 5][0] = sv; pr[tid >> 5][1] = sq; }
    }
    __syncthreads();
    if (tid == 0) {
        g_part[id][0] = pr[0][0] + pr[1][0];
        g_part[id][1] = pr[0][1] + pr[1][1];
    }
}

// ---------------------------------------------------------------------------
// K4b: finalize GN(1) stats from partials + channel attention. grid=16, 256 thr.
// ---------------------------------------------------------------------------
__global__ void k4b_attn(const float* __restrict__ gn, const float* __restrict__ btn,
                         const float* __restrict__ wq, const float* __restrict__ wk,
                         const float* __restrict__ wv) {
    int b = blockIdx.x >> 3;
    int head = blockIdx.x & 7;
    int c0 = head * 16;
    int tid = threadIdx.x;
    __shared__ float yn[16][513];
    __shared__ float ps[16][16];
    __shared__ float G[16][16];
    __shared__ float vmean[16];
    __shared__ double rs[8], rq[8];
    __shared__ float stat[2];

    // reduce this batch's 1024 partials (fixed order -> deterministic)
    double s = 0.0, q = 0.0;
    for (int i = tid; i < 1024; i += 256) {
        s += g_part[b * 1024 + i][0];
        q += g_part[b * 1024 + i][1];
    }
#pragma unroll
    for (int o = 16; o; o >>= 1) {
        s += __shfl_down_sync(0xffffffffu, s, o);
        q += __shfl_down_sync(0xffffffffu, q, o);
    }
    if ((tid & 31) == 0) { rs[tid >> 5] = s; rq[tid >> 5] = q; }
    __syncthreads();
    if (tid == 0) {
        double S = 0.0, Q = 0.0;
        for (int i = 0; i < 8; ++i) { S += rs[i]; Q += rq[i]; }
        double n = (double)(CC * SLEN);
        double mu = S / n;
        double var = Q / n - mu * mu;
        stat[0] = (float)mu;
        stat[1] = (float)(1.0 / sqrt(var + 1e-5));
    }
    __syncthreads();
    float mu = stat[0], rstd = stat[1];

    for (int i = tid; i < 16 * SLEN; i += 256) {
        int j = i >> 9, sp = i & 511;
        int c = c0 + j;
        yn[j][sp] = (g_y[b][c][sp] - mu) * rstd * gn[c] + btn[c];
    }
    __syncthreads();
    {
        int j = tid >> 4, seg = tid & 15;
        float t = 0.f;
        for (int u = 0; u < 32; ++u) t += yn[j][seg * 32 + u];
        ps[j][seg] = t;
    }
    __syncthreads();
    if (tid < 16) {
        float t = 0.f;
        for (int i = 0; i < 16; ++i) t += ps[tid][i];
        vmean[tid] = wv[c0 + tid] * t * (1.0f / 512.0f);
    }
    {
        int i = tid >> 4, j = tid & 15;
        float acc = 0.f;
        for (int sp = 0; sp < SLEN; ++sp) acc += yn[i][sp] * yn[j][sp];
        G[i][j] = acc;
    }
    __syncthreads();
    if (tid < 16) {
        int i = tid;
        float qi = wq[c0 + i] * 0.25f;  // includes HD^-0.5
        float sc[16];
        float m = -1e30f;
#pragma unroll
        for (int j = 0; j < 16; ++j) {
            sc[j] = qi * wk[c0 + j] * G[i][j];
            m = fmaxf(m, sc[j]);
        }
        float sum = 0.f;
#pragma unroll
        for (int j = 0; j < 16; ++j) {
            sc[j] = expf(sc[j] - m);
            sum += sc[j];
        }
        float o = 0.f;
#pragma unroll
        for (int j = 0; j < 16; ++j) o += sc[j] * vmean[j];
        o /= sum;
        g_ca[b][c0 + i] = 1.f / (1.f + expf(-o));
    }
}

// ---------------------------------------------------------------------------
// K5: out = x * gd*gh*gw*ca, fully vectorized float4, 100% lane efficiency.
// grid = 256 (one block per b,c), 512 threads.
// ---------------------------------------------------------------------------
__global__ void k5_gate_out(const float* __restrict__ x, float* __restrict__ out) {
    int bc = blockIdx.x;
    int b = bc >> 7, c = bc & 127;
    const float4* xp = reinterpret_cast<const float4*>(x + (size_t)bc * SP);
    float4* op = reinterpret_cast<float4*>(out + (size_t)bc * SP);

    __shared__ float sgd[LL], sgh[LL], sgw[LL];
    int tid = threadIdx.x;
    if (tid < LL) {
        float ca = g_ca[b][c];
        sgd[tid] = g_gate[0][b][c][tid] * ca;
        sgh[tid] = g_gate[1][b][c][tid];
        sgw[tid] = g_gate[2][b][c][tid];
    }
    __syncthreads();

    // SP/4 = 43904 float4 elements; per row 14 float4s (56 floats)
    for (int i = tid; i < 43904; i += 512) {
        int d = i / 784;               // 784 = 3136/4 float4 per d-plane
        int rem = i - d * 784;
        int h = rem / 14;
        int w4 = (rem - h * 14) * 4;
        float g = sgd[d] * sgh[h];
        float4 v = xp[i];
        v.x *= g * sgw[w4];
        v.y *= g * sgw[w4 + 1];
        v.z *= g * sgw[w4 + 2];
        v.w *= g * sgw[w4 + 3];
        op[i] = v;
    }
}

// ---------------------------------------------------------------------------
extern "C" void kernel_launch(void* const* d_in, const int* in_sizes, int n_in,
                              void* d_out, int out_size) {
    const float* x = (const float*)d_in[0];
    float* out = (float*)d_out;

    k1_axis_means<<<BB * CC, dim3(64, 8)>>>(x);
    k2_gates<<<24, 256>>>(
        (const float*)d_in[1], (const float*)d_in[2],
        (const float*)d_in[3], (const float*)d_in[4],
        (const float*)d_in[5], (const float*)d_in[6],
        (const float*)d_in[7], (const float*)d_in[8],
        (const float*)d_in[9], (const float*)d_in[10],
        (const float*)d_in[11], (const float*)d_in[12],
        (const float*)d_in[13], (const float*)d_in[14]);
    k3_pool<<<BB * CC * 8, dim3(64, 8)>>>(x);
    k4b_attn<<<BB * 8, 256>>>(
        (const float*)d_in[15], (const float*)d_in[16],
        (const float*)d_in[17], (const float*)d_in[18],
        (const float*)d_in[19]);
    k5_gate_out<<<BB * CC, 512>>>(x, out);
}